// round 3
// baseline (speedup 1.0000x reference)
#include <cuda_runtime.h>
#include <cuda_bf16.h>
#include <math.h>

// Problem constants (shapes fixed by the reference)
#define NMAX 100000
#define EMAX 3200000
#define C1 256
#define C2 512
#define CH 4096
#define CO 6

// ---------------- scratch (device globals; no allocation allowed) ----------------
__device__ float d_xws1[(size_t)NMAX * C1];   // (x@W1)*dinv[row]
__device__ float d_agg1[(size_t)NMAX * C1];
__device__ float d_y1  [(size_t)NMAX * C1];
__device__ float d_xws2[(size_t)NMAX * C2];
__device__ float d_agg2[(size_t)NMAX * C2];
__device__ float d_y2  [(size_t)NMAX * C2];
__device__ int   d_deg[NMAX];
__device__ float d_dinv[NMAX];
__device__ int   d_rowptr[NMAX + 1];
__device__ int   d_cursor[NMAX];
__device__ int   d_colidx[EMAX];
__device__ float d_sum[C2];
__device__ float d_sq[C2];
__device__ float d_scale[C2];
__device__ float d_shift[C2];
__device__ int   d_is64;

// ---------------- edge dtype detection ----------------
// int64 edge ids < 2^31 => every odd 32-bit word is 0. int32 edges => odd
// words are random node ids (virtually never all zero over 256 samples).
__global__ void k_detect(const unsigned* __restrict__ w, int nwords) {
    __shared__ int any_nz;
    if (threadIdx.x == 0) any_nz = 0;
    __syncthreads();
    int idx = 2 * threadIdx.x + 1;          // odd words among first 512
    if (idx < nwords && w[idx] != 0u) atomicOr(&any_nz, 1);
    __syncthreads();
    if (threadIdx.x == 0) d_is64 = any_nz ? 0 : 1;
}

__device__ __forceinline__ int edge_at(const void* ei, int E, int half, int i) {
    // half: 0 = src, 1 = dst
    if (d_is64) return (int)((const long long*)ei)[(size_t)half * E + i];
    return ((const int*)ei)[(size_t)half * E + i];
}

// ---------------- graph prep ----------------
__global__ void k_init(int n) {
    int i = blockIdx.x * blockDim.x + threadIdx.x;
    if (i < n) { d_deg[i] = 1; d_cursor[i] = 0; }
    if (i < C2) { d_sum[i] = 0.f; d_sq[i] = 0.f; }
}

__global__ void k_count(const void* __restrict__ ei, int E, int n) {
    int i = blockIdx.x * blockDim.x + threadIdx.x;
    if (i < E) {
        unsigned d = (unsigned)edge_at(ei, E, 1, i);
        if (d < (unsigned)n) atomicAdd(&d_deg[d], 1);
    }
}

__global__ void k_dinv(int n) {
    int i = blockIdx.x * blockDim.x + threadIdx.x;
    if (i < n) d_dinv[i] = rsqrtf((float)d_deg[i]);
}

// exclusive scan of (deg-1) -> rowptr; single block of 1024 threads
__global__ void k_scan(int n) {
    __shared__ int warp_sums[32];
    int lane = threadIdx.x & 31, wid = threadIdx.x >> 5;
    int carry = 0;
    if (threadIdx.x == 0) d_rowptr[0] = 0;
    for (int base = 0; base < n; base += 1024) {
        int i = base + threadIdx.x;
        int v = (i < n) ? (d_deg[i] - 1) : 0;
        int x = v;
        #pragma unroll
        for (int o = 1; o < 32; o <<= 1) {
            int t = __shfl_up_sync(0xffffffffu, x, o);
            if (lane >= o) x += t;
        }
        if (lane == 31) warp_sums[wid] = x;
        __syncthreads();
        if (wid == 0) {
            int w = warp_sums[lane];
            #pragma unroll
            for (int o = 1; o < 32; o <<= 1) {
                int t = __shfl_up_sync(0xffffffffu, w, o);
                if (lane >= o) w += t;
            }
            warp_sums[lane] = w;
        }
        __syncthreads();
        int incl = x + (wid > 0 ? warp_sums[wid - 1] : 0);
        if (i < n) d_rowptr[i + 1] = carry + incl;
        carry += warp_sums[31];
        __syncthreads();
    }
}

__global__ void k_fill(const void* __restrict__ ei, int E, int n) {
    int i = blockIdx.x * blockDim.x + threadIdx.x;
    if (i < E) {
        unsigned d = (unsigned)edge_at(ei, E, 1, i);
        unsigned s = (unsigned)edge_at(ei, E, 0, i);
        if (d < (unsigned)n && s < (unsigned)n) {
            int pos = atomicAdd(&d_cursor[d], 1);
            d_colidx[d_rowptr[d] + pos] = (int)s;
        }
    }
}

// ---------------- generic 64x64x16 fp32 GEMM, epilogue: * dinv[row] ----------------
__launch_bounds__(256)
__global__ void k_gemm(const float* __restrict__ A, const float* __restrict__ B,
                       float* __restrict__ C, int M, int K, int Nc) {
    __shared__ float As[64][17];
    __shared__ float Bs[16][64];
    int tid = threadIdx.x;
    int tx = tid & 15, ty = tid >> 4;
    int row0 = blockIdx.y * 64;
    int col0 = blockIdx.x * 64;
    float acc[4][4] = {};
    for (int k0 = 0; k0 < K; k0 += 16) {
        {
            int r = tid >> 4, kk = tid & 15;
            #pragma unroll
            for (int q = 0; q < 4; q++) {
                int rr = r + 16 * q;
                int grow = row0 + rr;
                As[rr][kk] = (grow < M) ? A[(size_t)grow * K + k0 + kk] : 0.f;
            }
        }
        {
            int kk = tid >> 6, c = tid & 63;
            #pragma unroll
            for (int q = 0; q < 4; q++)
                Bs[kk + 4 * q][c] = B[(size_t)(k0 + kk + 4 * q) * Nc + col0 + c];
        }
        __syncthreads();
        #pragma unroll
        for (int kk = 0; kk < 16; kk++) {
            float a[4], b[4];
            #pragma unroll
            for (int i = 0; i < 4; i++) a[i] = As[ty + 16 * i][kk];
            #pragma unroll
            for (int j = 0; j < 4; j++) b[j] = Bs[kk][tx + 16 * j];
            #pragma unroll
            for (int i = 0; i < 4; i++)
                #pragma unroll
                for (int j = 0; j < 4; j++)
                    acc[i][j] += a[i] * b[j];
        }
        __syncthreads();
    }
    #pragma unroll
    for (int i = 0; i < 4; i++) {
        int grow = row0 + ty + 16 * i;
        if (grow < M) {
            float f = d_dinv[grow];
            #pragma unroll
            for (int j = 0; j < 4; j++)
                C[(size_t)grow * Nc + col0 + tx + 16 * j] = acc[i][j] * f;
        }
    }
}

// ---------------- CSR gather aggregation + BN stats ----------------
template <int C>
__launch_bounds__(256)
__global__ void k_gather(const float* __restrict__ xws, float* __restrict__ agg, int N) {
    const int F = C / 32;
    int lane = threadIdx.x & 31;
    int warp = blockIdx.x * 8 + (threadIdx.x >> 5);
    int nwarps = gridDim.x * 8;
    float wsum[F], wsq[F];
    #pragma unroll
    for (int f = 0; f < F; f++) { wsum[f] = 0.f; wsq[f] = 0.f; }
    for (int v = warp; v < N; v += nwarps) {
        float acc[F];
        const float* self = xws + (size_t)v * C;
        #pragma unroll
        for (int f = 0; f < F; f++) acc[f] = self[lane + 32 * f];
        int e0 = d_rowptr[v], e1 = d_rowptr[v + 1];
        for (int e = e0; e < e1; e++) {
            int s = d_colidx[e];
            const float* p = xws + (size_t)s * C;
            #pragma unroll
            for (int f = 0; f < F; f++) acc[f] += p[lane + 32 * f];
        }
        float dv = d_dinv[v];
        float* o = agg + (size_t)v * C;
        #pragma unroll
        for (int f = 0; f < F; f++) {
            float val = acc[f] * dv;
            o[lane + 32 * f] = val;
            wsum[f] += val;
            wsq[f] += val * val;
        }
    }
    #pragma unroll
    for (int f = 0; f < F; f++) {
        atomicAdd(&d_sum[lane + 32 * f], wsum[f]);
        atomicAdd(&d_sq[lane + 32 * f], wsq[f]);
    }
}

// ---------------- BN finalize (also clears stats for next layer) ----------------
__global__ void k_bnfin(const float* __restrict__ g, const float* __restrict__ be,
                        int C, float invN) {
    int c = blockIdx.x * blockDim.x + threadIdx.x;
    if (c < C) {
        float m = d_sum[c] * invN;
        float var = d_sq[c] * invN - m * m;
        float r = rsqrtf(var + 1e-5f);
        float sc = g[c] * r;
        d_scale[c] = sc;
        d_shift[c] = be[c] - m * sc;
        d_sum[c] = 0.f;
        d_sq[c] = 0.f;
    }
}

// ---------------- elementwise BN-apply + LeakyReLU (float4) ----------------
__global__ void k_bnrelu(const float* __restrict__ agg, float* __restrict__ y,
                         size_t n4, int C) {
    size_t i = (size_t)blockIdx.x * blockDim.x + threadIdx.x;
    if (i < n4) {
        size_t idx = i * 4;
        int c = (int)(idx % C);
        float4 v = *(const float4*)(agg + idx);
        float4 r;
        r.x = v.x * d_scale[c]     + d_shift[c];
        r.y = v.y * d_scale[c + 1] + d_shift[c + 1];
        r.z = v.z * d_scale[c + 2] + d_shift[c + 2];
        r.w = v.w * d_scale[c + 3] + d_shift[c + 3];
        r.x = r.x >= 0.f ? r.x : 0.01f * r.x;
        r.y = r.y >= 0.f ? r.y : 0.01f * r.y;
        r.z = r.z >= 0.f ? r.z : 0.01f * r.z;
        r.w = r.w >= 0.f ? r.w : 0.01f * r.w;
        *(float4*)(y + idx) = r;
    }
}

// ---------------- fused MLP: y2 @ Wd1 (+bd1, leaky) @ Wd2 (+bd2) -> softmax ----------------
// block = 64 rows; streams Wd1 in 128-col chunks; h never materialized.
__launch_bounds__(256, 2)
__global__ void k_mlp(const float* __restrict__ y2, const float* __restrict__ Wd1,
                      const float* __restrict__ bd1, const float* __restrict__ Wd2,
                      const float* __restrict__ bd2, float* __restrict__ out, int M) {
    __shared__ float As[64][17];
    __shared__ float Bs[16][128];
    __shared__ float slog[64][CO];
    int tid = threadIdx.x;
    int tx = tid & 15, ty = tid >> 4;
    int row0 = blockIdx.x * 64;
    float logit[4][CO];
    #pragma unroll
    for (int i = 0; i < 4; i++)
        #pragma unroll
        for (int j = 0; j < CO; j++) logit[i][j] = 0.f;

    for (int cn = 0; cn < CH; cn += 128) {
        float acc[4][8];
        #pragma unroll
        for (int i = 0; i < 4; i++)
            #pragma unroll
            for (int u = 0; u < 8; u++) acc[i][u] = 0.f;

        for (int k0 = 0; k0 < C2; k0 += 16) {
            {
                int r = tid >> 4, kk = tid & 15;
                #pragma unroll
                for (int q = 0; q < 4; q++) {
                    int grow = row0 + r + 16 * q;
                    As[r + 16 * q][kk] = (grow < M) ? y2[(size_t)grow * C2 + k0 + kk] : 0.f;
                }
            }
            {
                #pragma unroll
                for (int q = 0; q < 8; q++) {
                    int idx = tid + 256 * q;
                    int kk = idx >> 7, c = idx & 127;
                    Bs[kk][c] = Wd1[(size_t)(k0 + kk) * CH + cn + c];
                }
            }
            __syncthreads();
            #pragma unroll
            for (int kk = 0; kk < 16; kk++) {
                float a[4], b[8];
                #pragma unroll
                for (int i = 0; i < 4; i++) a[i] = As[ty + 16 * i][kk];
                #pragma unroll
                for (int u = 0; u < 8; u++) b[u] = Bs[kk][tx + 16 * u];
                #pragma unroll
                for (int i = 0; i < 4; i++)
                    #pragma unroll
                    for (int u = 0; u < 8; u++)
                        acc[i][u] += a[i] * b[u];
            }
            __syncthreads();
        }
        // chunk epilogue: bias + leaky + fold into logits via Wd2
        #pragma unroll
        for (int u = 0; u < 8; u++) {
            int c = cn + tx + 16 * u;
            float bb = __ldg(&bd1[c]);
            #pragma unroll
            for (int i = 0; i < 4; i++) {
                float h = acc[i][u] + bb;
                h = h >= 0.f ? h : 0.01f * h;
                #pragma unroll
                for (int j = 0; j < CO; j++)
                    logit[i][j] += h * __ldg(&Wd2[(size_t)c * CO + j]);
            }
        }
    }

    // reduce logits across tx via shared atomics
    for (int i = tid; i < 64 * CO; i += 256) ((float*)slog)[i] = 0.f;
    __syncthreads();
    #pragma unroll
    for (int i = 0; i < 4; i++)
        #pragma unroll
        for (int j = 0; j < CO; j++)
            atomicAdd(&slog[ty + 16 * i][j], logit[i][j]);
    __syncthreads();

    if (tid < 64) {
        int grow = row0 + tid;
        if (grow < M) {
            float l[CO];
            float mx = -1e30f;
            #pragma unroll
            for (int j = 0; j < CO; j++) {
                l[j] = slog[tid][j] + bd2[j];
                mx = fmaxf(mx, l[j]);
            }
            float s = 0.f;
            #pragma unroll
            for (int j = 0; j < CO; j++) { l[j] = expf(l[j] - mx); s += l[j]; }
            float inv = 1.f / s;
            #pragma unroll
            for (int j = 0; j < CO; j++)
                out[(size_t)grow * CO + j] = l[j] * inv;
        }
    }
}

// ---------------- launch ----------------
extern "C" void kernel_launch(void* const* d_in, const int* in_sizes, int n_in,
                              void* d_out, int out_size) {
    const float* x   = (const float*)d_in[0];
    const void*  ei  = d_in[1];                  // edge_index: int32 or int64, auto-detected
    const float* W1  = (const float*)d_in[2];
    const float* W2  = (const float*)d_in[4];
    const float* g1  = (const float*)d_in[6];
    const float* be1 = (const float*)d_in[7];
    const float* g2  = (const float*)d_in[8];
    const float* be2 = (const float*)d_in[9];
    const float* Wd1 = (const float*)d_in[10];
    const float* bd1 = (const float*)d_in[11];
    const float* Wd2 = (const float*)d_in[12];
    const float* bd2 = (const float*)d_in[13];
    float* out = (float*)d_out;

    int N = in_sizes[0] / 128;
    int E = in_sizes[1] / 2;

    float *p_xws1, *p_agg1, *p_y1, *p_xws2, *p_agg2, *p_y2;
    cudaGetSymbolAddress((void**)&p_xws1, d_xws1);
    cudaGetSymbolAddress((void**)&p_agg1, d_agg1);
    cudaGetSymbolAddress((void**)&p_y1,   d_y1);
    cudaGetSymbolAddress((void**)&p_xws2, d_xws2);
    cudaGetSymbolAddress((void**)&p_agg2, d_agg2);
    cudaGetSymbolAddress((void**)&p_y2,   d_y2);

    // graph prep
    k_detect<<<1, 256>>>((const unsigned*)ei, 2 * E);   // min words: int32 layout
    k_init<<<(N + 255) / 256, 256>>>(N);
    k_count<<<(E + 255) / 256, 256>>>(ei, E, N);
    k_dinv<<<(N + 255) / 256, 256>>>(N);
    k_scan<<<1, 1024>>>(N);
    k_fill<<<(E + 255) / 256, 256>>>(ei, E, N);

    int rowTiles = (N + 63) / 64;
    float invN = 1.0f / (float)N;

    // layer 1
    k_gemm<<<dim3(C1 / 64, rowTiles), 256>>>(x, W1, p_xws1, N, 128, C1);
    k_gather<C1><<<1184, 256>>>(p_xws1, p_agg1, N);
    k_bnfin<<<1, 256>>>(g1, be1, C1, invN);
    k_bnrelu<<<(int)(((size_t)N * C1 / 4 + 255) / 256), 256>>>(p_agg1, p_y1, (size_t)N * C1 / 4, C1);

    // layer 2
    k_gemm<<<dim3(C2 / 64, rowTiles), 256>>>(p_y1, W2, p_xws2, N, C1, C2);
    k_gather<C2><<<1184, 256>>>(p_xws2, p_agg2, N);
    k_bnfin<<<2, 256>>>(g2, be2, C2, invN);
    k_bnrelu<<<(int)(((size_t)N * C2 / 4 + 255) / 256), 256>>>(p_agg2, p_y2, (size_t)N * C2 / 4, C2);

    // fused MLP + softmax
    k_mlp<<<rowTiles, 256>>>(p_y2, Wd1, bd1, Wd2, bd2, out, N);
}

// round 14
// speedup vs baseline: 1.4181x; 1.4181x over previous
#include <cuda_runtime.h>
#include <cuda_bf16.h>
#include <math.h>

// Problem constants (shapes fixed by the reference)
#define NMAX 100000
#define EMAX 3200000
#define C1 256
#define C2 512
#define CH 4096
#define CO 6

// ---------------- scratch (device globals; no allocation allowed) ----------------
__device__ float d_xws1[(size_t)NMAX * C1];   // (x@W1)*dinv[row]
__device__ float d_agg1[(size_t)NMAX * C1];
__device__ float d_y1  [(size_t)NMAX * C1];
__device__ float d_xws2[(size_t)NMAX * C2];
__device__ float d_agg2[(size_t)NMAX * C2];
__device__ float d_y2  [(size_t)NMAX * C2];
__device__ int   d_deg[NMAX];
__device__ float d_dinv[NMAX];
__device__ int   d_rowptr[NMAX + 1];
__device__ int   d_cursor[NMAX];
__device__ int   d_colidx[EMAX];
__device__ float d_sum[C2];
__device__ float d_sq[C2];
__device__ float d_scale[C2];
__device__ float d_shift[C2];
__device__ int   d_is64;

// ---------------- edge dtype detection ----------------
__global__ void k_detect(const unsigned* __restrict__ w, int nwords) {
    __shared__ int any_nz;
    if (threadIdx.x == 0) any_nz = 0;
    __syncthreads();
    int idx = 2 * threadIdx.x + 1;
    if (idx < nwords && w[idx] != 0u) atomicOr(&any_nz, 1);
    __syncthreads();
    if (threadIdx.x == 0) d_is64 = any_nz ? 0 : 1;
}

__device__ __forceinline__ int edge_at(const void* ei, int E, int half, int i) {
    if (d_is64) return (int)((const long long*)ei)[(size_t)half * E + i];
    return ((const int*)ei)[(size_t)half * E + i];
}

// ---------------- graph prep ----------------
__global__ void k_init(int n) {
    int i = blockIdx.x * blockDim.x + threadIdx.x;
    if (i < n) { d_deg[i] = 1; d_cursor[i] = 0; }
    if (i < C2) { d_sum[i] = 0.f; d_sq[i] = 0.f; }
}

__global__ void k_count(const void* __restrict__ ei, int E, int n) {
    int i = blockIdx.x * blockDim.x + threadIdx.x;
    if (i < E) {
        unsigned d = (unsigned)edge_at(ei, E, 1, i);
        if (d < (unsigned)n) atomicAdd(&d_deg[d], 1);
    }
}

__global__ void k_dinv(int n) {
    int i = blockIdx.x * blockDim.x + threadIdx.x;
    if (i < n) d_dinv[i] = rsqrtf((float)d_deg[i]);
}

__global__ void k_scan(int n) {
    __shared__ int warp_sums[32];
    int lane = threadIdx.x & 31, wid = threadIdx.x >> 5;
    int carry = 0;
    if (threadIdx.x == 0) d_rowptr[0] = 0;
    for (int base = 0; base < n; base += 1024) {
        int i = base + threadIdx.x;
        int v = (i < n) ? (d_deg[i] - 1) : 0;
        int x = v;
        #pragma unroll
        for (int o = 1; o < 32; o <<= 1) {
            int t = __shfl_up_sync(0xffffffffu, x, o);
            if (lane >= o) x += t;
        }
        if (lane == 31) warp_sums[wid] = x;
        __syncthreads();
        if (wid == 0) {
            int w = warp_sums[lane];
            #pragma unroll
            for (int o = 1; o < 32; o <<= 1) {
                int t = __shfl_up_sync(0xffffffffu, w, o);
                if (lane >= o) w += t;
            }
            warp_sums[lane] = w;
        }
        __syncthreads();
        int incl = x + (wid > 0 ? warp_sums[wid - 1] : 0);
        if (i < n) d_rowptr[i + 1] = carry + incl;
        carry += warp_sums[31];
        __syncthreads();
    }
}

__global__ void k_fill(const void* __restrict__ ei, int E, int n) {
    int i = blockIdx.x * blockDim.x + threadIdx.x;
    if (i < E) {
        unsigned d = (unsigned)edge_at(ei, E, 1, i);
        unsigned s = (unsigned)edge_at(ei, E, 0, i);
        if (d < (unsigned)n && s < (unsigned)n) {
            int pos = atomicAdd(&d_cursor[d], 1);
            d_colidx[d_rowptr[d] + pos] = (int)s;
        }
    }
}

// ---------------- generic 64x64x16 fp32 GEMM (fallback, currently unused) ----------------
__launch_bounds__(256)
__global__ void k_gemm(const float* __restrict__ A, const float* __restrict__ B,
                       float* __restrict__ C, int M, int K, int Nc) {
    __shared__ float As[64][17];
    __shared__ float Bs[16][64];
    int tid = threadIdx.x;
    int tx = tid & 15, ty = tid >> 4;
    int row0 = blockIdx.y * 64;
    int col0 = blockIdx.x * 64;
    float acc[4][4] = {};
    for (int k0 = 0; k0 < K; k0 += 16) {
        {
            int r = tid >> 4, kk = tid & 15;
            #pragma unroll
            for (int q = 0; q < 4; q++) {
                int rr = r + 16 * q;
                int grow = row0 + rr;
                As[rr][kk] = (grow < M) ? A[(size_t)grow * K + k0 + kk] : 0.f;
            }
        }
        {
            int kk = tid >> 6, c = tid & 63;
            #pragma unroll
            for (int q = 0; q < 4; q++)
                Bs[kk + 4 * q][c] = B[(size_t)(k0 + kk + 4 * q) * Nc + col0 + c];
        }
        __syncthreads();
        #pragma unroll
        for (int kk = 0; kk < 16; kk++) {
            float a[4], b[4];
            #pragma unroll
            for (int i = 0; i < 4; i++) a[i] = As[ty + 16 * i][kk];
            #pragma unroll
            for (int j = 0; j < 4; j++) b[j] = Bs[kk][tx + 16 * j];
            #pragma unroll
            for (int i = 0; i < 4; i++)
                #pragma unroll
                for (int j = 0; j < 4; j++)
                    acc[i][j] += a[i] * b[j];
        }
        __syncthreads();
    }
    #pragma unroll
    for (int i = 0; i < 4; i++) {
        int grow = row0 + ty + 16 * i;
        if (grow < M) {
            float f = d_dinv[grow];
            #pragma unroll
            for (int j = 0; j < 4; j++)
                C[(size_t)grow * Nc + col0 + tx + 16 * j] = acc[i][j] * f;
        }
    }
}

// ---------------- CSR gather aggregation + BN stats (float4, 2x edge ILP) ----------------
// Lane handles columns 4*lane + 128*f + {0..3}; warp covers C columns exactly once.
template <int C>
__launch_bounds__(256)
__global__ void k_gather(const float* __restrict__ xws, float* __restrict__ agg, int N) {
    const int F4 = C / 128;   // float4s per lane: C1=256 -> 2, C2=512 -> 4
    int lane = threadIdx.x & 31;
    int warp = blockIdx.x * 8 + (threadIdx.x >> 5);
    int nwarps = gridDim.x * 8;
    float4 wsum[F4], wsq[F4];
    #pragma unroll
    for (int f = 0; f < F4; f++) {
        wsum[f] = make_float4(0.f, 0.f, 0.f, 0.f);
        wsq[f]  = make_float4(0.f, 0.f, 0.f, 0.f);
    }
    for (int v = warp; v < N; v += nwarps) {
        float4 acc[F4];
        const float4* self = (const float4*)(xws + (size_t)v * C);
        #pragma unroll
        for (int f = 0; f < F4; f++) acc[f] = self[lane + 32 * f];
        int e0 = d_rowptr[v], e1 = d_rowptr[v + 1];
        int e = e0;
        // 2x unrolled: two independent neighbor-row load streams in flight
        for (; e + 1 < e1; e += 2) {
            int s0 = d_colidx[e];
            int s1 = d_colidx[e + 1];
            const float4* p0 = (const float4*)(xws + (size_t)s0 * C);
            const float4* p1 = (const float4*)(xws + (size_t)s1 * C);
            #pragma unroll
            for (int f = 0; f < F4; f++) {
                float4 q0 = p0[lane + 32 * f];
                float4 q1 = p1[lane + 32 * f];
                acc[f].x += q0.x + q1.x;
                acc[f].y += q0.y + q1.y;
                acc[f].z += q0.z + q1.z;
                acc[f].w += q0.w + q1.w;
            }
        }
        if (e < e1) {
            int s = d_colidx[e];
            const float4* p = (const float4*)(xws + (size_t)s * C);
            #pragma unroll
            for (int f = 0; f < F4; f++) {
                float4 q = p[lane + 32 * f];
                acc[f].x += q.x; acc[f].y += q.y; acc[f].z += q.z; acc[f].w += q.w;
            }
        }
        float dv = d_dinv[v];
        float4* o = (float4*)(agg + (size_t)v * C);
        #pragma unroll
        for (int f = 0; f < F4; f++) {
            float4 val;
            val.x = acc[f].x * dv; val.y = acc[f].y * dv;
            val.z = acc[f].z * dv; val.w = acc[f].w * dv;
            o[lane + 32 * f] = val;
            wsum[f].x += val.x; wsum[f].y += val.y; wsum[f].z += val.z; wsum[f].w += val.w;
            wsq[f].x += val.x * val.x; wsq[f].y += val.y * val.y;
            wsq[f].z += val.z * val.z; wsq[f].w += val.w * val.w;
        }
    }
    #pragma unroll
    for (int f = 0; f < F4; f++) {
        int c0 = 4 * lane + 128 * f;
        atomicAdd(&d_sum[c0 + 0], wsum[f].x);
        atomicAdd(&d_sum[c0 + 1], wsum[f].y);
        atomicAdd(&d_sum[c0 + 2], wsum[f].z);
        atomicAdd(&d_sum[c0 + 3], wsum[f].w);
        atomicAdd(&d_sq[c0 + 0], wsq[f].x);
        atomicAdd(&d_sq[c0 + 1], wsq[f].y);
        atomicAdd(&d_sq[c0 + 2], wsq[f].z);
        atomicAdd(&d_sq[c0 + 3], wsq[f].w);
    }
}

// ---------------- BN finalize ----------------
__global__ void k_bnfin(const float* __restrict__ g, const float* __restrict__ be,
                        int C, float invN) {
    int c = blockIdx.x * blockDim.x + threadIdx.x;
    if (c < C) {
        float m = d_sum[c] * invN;
        float var = d_sq[c] * invN - m * m;
        float r = rsqrtf(var + 1e-5f);
        float sc = g[c] * r;
        d_scale[c] = sc;
        d_shift[c] = be[c] - m * sc;
        d_sum[c] = 0.f;
        d_sq[c] = 0.f;
    }
}

// ---------------- elementwise BN-apply + LeakyReLU (float4) ----------------
__global__ void k_bnrelu(const float* __restrict__ agg, float* __restrict__ y,
                         size_t n4, int C) {
    size_t i = (size_t)blockIdx.x * blockDim.x + threadIdx.x;
    if (i < n4) {
        size_t idx = i * 4;
        int c = (int)(idx % C);
        float4 v = *(const float4*)(agg + idx);
        float4 r;
        r.x = v.x * d_scale[c]     + d_shift[c];
        r.y = v.y * d_scale[c + 1] + d_shift[c + 1];
        r.z = v.z * d_scale[c + 2] + d_shift[c + 2];
        r.w = v.w * d_scale[c + 3] + d_shift[c + 3];
        r.x = r.x >= 0.f ? r.x : 0.01f * r.x;
        r.y = r.y >= 0.f ? r.y : 0.01f * r.y;
        r.z = r.z >= 0.f ? r.z : 0.01f * r.z;
        r.w = r.w >= 0.f ? r.w : 0.01f * r.w;
        *(float4*)(y + idx) = r;
    }
}

// ---------------- tf32 helpers ----------------
__device__ __forceinline__ unsigned f2tf(float x) {
    unsigned u;
    asm("cvt.rna.tf32.f32 %0, %1;" : "=r"(u) : "f"(x));
    return u;
}

__device__ __forceinline__ void mma_tf32(float* d, const unsigned* a, const unsigned* b) {
    asm volatile(
        "mma.sync.aligned.m16n8k8.row.col.f32.tf32.tf32.f32 "
        "{%0,%1,%2,%3}, {%4,%5,%6,%7}, {%8,%9}, {%0,%1,%2,%3};"
        : "+f"(d[0]), "+f"(d[1]), "+f"(d[2]), "+f"(d[3])
        : "r"(a[0]), "r"(a[1]), "r"(a[2]), "r"(a[3]), "r"(b[0]), "r"(b[1]));
}

// ---------------- tf32 GEMM: C[M,Nc] = (A[M,K] @ B[K,Nc]) * dinv[row] ----------------
// BM=128, BN=64, BK=32; 8 warps 4(m)x2(n); warp tile 32x32 of m16n8k8 frags.
// Requires K % 32 == 0, Nc % 64 == 0.
__launch_bounds__(256, 2)
__global__ void k_gemm_tc(const float* __restrict__ A, const float* __restrict__ B,
                          float* __restrict__ C, int M, int K, int Nc) {
    __shared__ float As[128][33];
    __shared__ float Bs[32][65];
    int tid = threadIdx.x;
    int lane = tid & 31;
    int wid = tid >> 5;
    int g = lane >> 2;
    int t = lane & 3;
    int warp_m = wid & 3;
    int warp_n = wid >> 2;
    int row0 = blockIdx.y * 128;
    int col0 = blockIdx.x * 64;

    float acc[2][4][4];
    #pragma unroll
    for (int f = 0; f < 2; f++)
        #pragma unroll
        for (int u = 0; u < 4; u++)
            #pragma unroll
            for (int q = 0; q < 4; q++) acc[f][u][q] = 0.f;

    for (int k0 = 0; k0 < K; k0 += 32) {
        #pragma unroll
        for (int q = 0; q < 4; q++) {
            int slot = tid + 256 * q;
            int r = slot >> 3, c4 = (slot & 7) * 4;
            int grow = row0 + r;
            float4 v = make_float4(0.f, 0.f, 0.f, 0.f);
            if (grow < M) v = *(const float4*)(A + (size_t)grow * K + k0 + c4);
            As[r][c4 + 0] = __uint_as_float(f2tf(v.x));
            As[r][c4 + 1] = __uint_as_float(f2tf(v.y));
            As[r][c4 + 2] = __uint_as_float(f2tf(v.z));
            As[r][c4 + 3] = __uint_as_float(f2tf(v.w));
        }
        #pragma unroll
        for (int q = 0; q < 2; q++) {
            int slot = tid + 256 * q;
            int k = slot >> 4, c4 = (slot & 15) * 4;
            float4 v = *(const float4*)(B + (size_t)(k0 + k) * Nc + col0 + c4);
            Bs[k][c4 + 0] = __uint_as_float(f2tf(v.x));
            Bs[k][c4 + 1] = __uint_as_float(f2tf(v.y));
            Bs[k][c4 + 2] = __uint_as_float(f2tf(v.z));
            Bs[k][c4 + 3] = __uint_as_float(f2tf(v.w));
        }
        __syncthreads();

        #pragma unroll
        for (int kk = 0; kk < 32; kk += 8) {
            unsigned a[2][4], b[4][2];
            #pragma unroll
            for (int f = 0; f < 2; f++) {
                int r = warp_m * 32 + f * 16 + g;
                a[f][0] = __float_as_uint(As[r][kk + t]);
                a[f][1] = __float_as_uint(As[r + 8][kk + t]);
                a[f][2] = __float_as_uint(As[r][kk + t + 4]);
                a[f][3] = __float_as_uint(As[r + 8][kk + t + 4]);
            }
            #pragma unroll
            for (int u = 0; u < 4; u++) {
                int col = warp_n * 32 + u * 8 + g;
                b[u][0] = __float_as_uint(Bs[kk + t][col]);
                b[u][1] = __float_as_uint(Bs[kk + t + 4][col]);
            }
            #pragma unroll
            for (int f = 0; f < 2; f++)
                #pragma unroll
                for (int u = 0; u < 4; u++)
                    mma_tf32(acc[f][u], a[f], b[u]);
        }
        __syncthreads();
    }

    // epilogue: * dinv[row], write out
    #pragma unroll
    for (int f = 0; f < 2; f++) {
        int r0g = row0 + warp_m * 32 + f * 16 + g;
        #pragma unroll
        for (int u = 0; u < 4; u++) {
            int c = col0 + warp_n * 32 + u * 8 + 2 * t;
            if (r0g < M) {
                float dv = d_dinv[r0g];
                C[(size_t)r0g * Nc + c]     = acc[f][u][0] * dv;
                C[(size_t)r0g * Nc + c + 1] = acc[f][u][1] * dv;
            }
            if (r0g + 8 < M) {
                float dv8 = d_dinv[r0g + 8];
                C[(size_t)(r0g + 8) * Nc + c]     = acc[f][u][2] * dv8;
                C[(size_t)(r0g + 8) * Nc + c + 1] = acc[f][u][3] * dv8;
            }
        }
    }
}

// ---------------- fused MLP (tf32 tensor cores) ----------------
__launch_bounds__(256, 2)
__global__ void k_mlp_tc(const float* __restrict__ y2, const float* __restrict__ Wd1,
                         const float* __restrict__ bd1, const float* __restrict__ Wd2,
                         const float* __restrict__ bd2, float* __restrict__ out, int M) {
    __shared__ float As[128][33];     // [row][k] tf32-rounded
    __shared__ float Bs[32][65];      // [k][col] tf32-rounded
    __shared__ float Wd2s[64][CO];
    __shared__ float bd1s[64];
    __shared__ float slog[128][CO];

    int tid = threadIdx.x;
    int lane = tid & 31;
    int wid = tid >> 5;
    int g = lane >> 2;
    int t = lane & 3;
    int warp_m = wid & 3;
    int warp_n = wid >> 2;
    int row0 = blockIdx.x * 128;

    float logit[4][CO];
    #pragma unroll
    for (int s = 0; s < 4; s++)
        #pragma unroll
        for (int j = 0; j < CO; j++) logit[s][j] = 0.f;

    for (int i = tid; i < 128 * CO; i += 256) ((float*)slog)[i] = 0.f;

    for (int cn = 0; cn < CH; cn += 64) {
        float acc[2][4][4];
        #pragma unroll
        for (int f = 0; f < 2; f++)
            #pragma unroll
            for (int u = 0; u < 4; u++)
                #pragma unroll
                for (int q = 0; q < 4; q++) acc[f][u][q] = 0.f;

        if (tid < 64) bd1s[tid] = bd1[cn + tid];
        for (int i = tid; i < 64 * CO; i += 256)
            ((float*)Wd2s)[i] = Wd2[(size_t)(cn + i / CO) * CO + (i % CO)];

        for (int k0 = 0; k0 < C2; k0 += 32) {
            #pragma unroll
            for (int q = 0; q < 4; q++) {
                int slot = tid + 256 * q;
                int r = slot >> 3, c4 = (slot & 7) * 4;
                int grow = row0 + r;
                float4 v = make_float4(0.f, 0.f, 0.f, 0.f);
                if (grow < M) v = *(const float4*)(y2 + (size_t)grow * C2 + k0 + c4);
                As[r][c4 + 0] = __uint_as_float(f2tf(v.x));
                As[r][c4 + 1] = __uint_as_float(f2tf(v.y));
                As[r][c4 + 2] = __uint_as_float(f2tf(v.z));
                As[r][c4 + 3] = __uint_as_float(f2tf(v.w));
            }
            #pragma unroll
            for (int q = 0; q < 2; q++) {
                int slot = tid + 256 * q;
                int k = slot >> 4, c4 = (slot & 15) * 4;
                float4 v = *(const float4*)(Wd1 + (size_t)(k0 + k) * CH + cn + c4);
                Bs[k][c4 + 0] = __uint_as_float(f2tf(v.x));
                Bs[k][c4 + 1] = __uint_as_float(f2tf(v.y));
                Bs[k][c4 + 2] = __uint_as_float(f2tf(v.z));
                Bs[k][c4 + 3] = __uint_as_float(f2tf(v.w));
            }
            __syncthreads();

            #pragma unroll
            for (int kk = 0; kk < 32; kk += 8) {
                unsigned a[2][4], b[4][2];
                #pragma unroll
                for (int f = 0; f < 2; f++) {
                    int r = warp_m * 32 + f * 16 + g;
                    a[f][0] = __float_as_uint(As[r][kk + t]);
                    a[f][1] = __float_as_uint(As[r + 8][kk + t]);
                    a[f][2] = __float_as_uint(As[r][kk + t + 4]);
                    a[f][3] = __float_as_uint(As[r + 8][kk + t + 4]);
                }
                #pragma unroll
                for (int u = 0; u < 4; u++) {
                    int col = warp_n * 32 + u * 8 + g;
                    b[u][0] = __float_as_uint(Bs[kk + t][col]);
                    b[u][1] = __float_as_uint(Bs[kk + t + 4][col]);
                }
                #pragma unroll
                for (int f = 0; f < 2; f++)
                    #pragma unroll
                    for (int u = 0; u < 4; u++)
                        mma_tf32(acc[f][u], a[f], b[u]);
            }
            __syncthreads();
        }

        // chunk epilogue: bias + leaky, fold into logits via Wd2s
        #pragma unroll
        for (int f = 0; f < 2; f++) {
            #pragma unroll
            for (int u = 0; u < 4; u++) {
                int cA = warp_n * 32 + u * 8 + 2 * t;
                float b0 = bd1s[cA], b1 = bd1s[cA + 1];
                float h00 = acc[f][u][0] + b0;
                float h01 = acc[f][u][1] + b1;
                float h10 = acc[f][u][2] + b0;
                float h11 = acc[f][u][3] + b1;
                h00 = h00 >= 0.f ? h00 : 0.01f * h00;
                h01 = h01 >= 0.f ? h01 : 0.01f * h01;
                h10 = h10 >= 0.f ? h10 : 0.01f * h10;
                h11 = h11 >= 0.f ? h11 : 0.01f * h11;
                #pragma unroll
                for (int j = 0; j < CO; j++) {
                    float w0 = Wd2s[cA][j], w1 = Wd2s[cA + 1][j];
                    logit[f * 2 + 0][j] += h00 * w0 + h01 * w1;
                    logit[f * 2 + 1][j] += h10 * w0 + h11 * w1;
                }
            }
        }
        __syncthreads();
    }

    // reduce logits: sum over the 4 t-lanes of each quad, then shared atomics
    #pragma unroll
    for (int s = 0; s < 4; s++)
        #pragma unroll
        for (int j = 0; j < CO; j++) {
            float v = logit[s][j];
            v += __shfl_xor_sync(0xffffffffu, v, 1);
            v += __shfl_xor_sync(0xffffffffu, v, 2);
            logit[s][j] = v;
        }
    if (t == 0) {
        #pragma unroll
        for (int f = 0; f < 2; f++) {
            int lr = warp_m * 32 + f * 16 + g;
            #pragma unroll
            for (int j = 0; j < CO; j++) {
                atomicAdd(&slog[lr][j], logit[f * 2 + 0][j]);
                atomicAdd(&slog[lr + 8][j], logit[f * 2 + 1][j]);
            }
        }
    }
    __syncthreads();

    if (tid < 128) {
        int grow = row0 + tid;
        if (grow < M) {
            float l[CO];
            float mx = -1e30f;
            #pragma unroll
            for (int j = 0; j < CO; j++) {
                l[j] = slog[tid][j] + bd2[j];
                mx = fmaxf(mx, l[j]);
            }
            float s = 0.f;
            #pragma unroll
            for (int j = 0; j < CO; j++) { l[j] = expf(l[j] - mx); s += l[j]; }
            float inv = 1.f / s;
            #pragma unroll
            for (int j = 0; j < CO; j++)
                out[(size_t)grow * CO + j] = l[j] * inv;
        }
    }
}

// ---------------- launch ----------------
extern "C" void kernel_launch(void* const* d_in, const int* in_sizes, int n_in,
                              void* d_out, int out_size) {
    const float* x   = (const float*)d_in[0];
    const void*  ei  = d_in[1];
    const float* W1  = (const float*)d_in[2];
    const float* W2  = (const float*)d_in[4];
    const float* g1  = (const float*)d_in[6];
    const float* be1 = (const float*)d_in[7];
    const float* g2  = (const float*)d_in[8];
    const float* be2 = (const float*)d_in[9];
    const float* Wd1 = (const float*)d_in[10];
    const float* bd1 = (const float*)d_in[11];
    const float* Wd2 = (const float*)d_in[12];
    const float* bd2 = (const float*)d_in[13];
    float* out = (float*)d_out;

    int N = in_sizes[0] / 128;
    int E = in_sizes[1] / 2;

    float *p_xws1, *p_agg1, *p_y1, *p_xws2, *p_agg2, *p_y2;
    cudaGetSymbolAddress((void**)&p_xws1, d_xws1);
    cudaGetSymbolAddress((void**)&p_agg1, d_agg1);
    cudaGetSymbolAddress((void**)&p_y1,   d_y1);
    cudaGetSymbolAddress((void**)&p_xws2, d_xws2);
    cudaGetSymbolAddress((void**)&p_agg2, d_agg2);
    cudaGetSymbolAddress((void**)&p_y2,   d_y2);

    // graph prep
    k_detect<<<1, 256>>>((const unsigned*)ei, 2 * E);
    k_init<<<(N + 255) / 256, 256>>>(N);
    k_count<<<(E + 255) / 256, 256>>>(ei, E, N);
    k_dinv<<<(N + 255) / 256, 256>>>(N);
    k_scan<<<1, 1024>>>(N);
    k_fill<<<(E + 255) / 256, 256>>>(ei, E, N);

    int rowTiles128 = (N + 127) / 128;
    float invN = 1.0f / (float)N;

    // layer 1 (tf32 tensor-core GEMM: 100k x 128 x 256; BN renormalizes tf32 error)
    k_gemm_tc<<<dim3(C1 / 64, rowTiles128), 256>>>(x, W1, p_xws1, N, 128, C1);
    k_gather<C1><<<1184, 256>>>(p_xws1, p_agg1, N);
    k_bnfin<<<1, 256>>>(g1, be1, C1, invN);
    k_bnrelu<<<(int)(((size_t)N * C1 / 4 + 255) / 256), 256>>>(p_agg1, p_y1, (size_t)N * C1 / 4, C1);

    // layer 2 (tf32 tensor-core GEMM: 100k x 256 x 512)
    k_gemm_tc<<<dim3(C2 / 64, rowTiles128), 256>>>(p_y1, W2, p_xws2, N, C1, C2);
    k_gather<C2><<<1184, 256>>>(p_xws2, p_agg2, N);
    k_bnfin<<<2, 256>>>(g2, be2, C2, invN);
    k_bnrelu<<<(int)(((size_t)N * C2 / 4 + 255) / 256), 256>>>(p_agg2, p_y2, (size_t)N * C2 / 4, C2);

    // fused MLP + softmax (tf32 tensor cores)
    k_mlp_tc<<<rowTiles128, 256>>>(p_y2, Wd1, bd1, Wd2, bd2, out, N);
}